// round 7
// baseline (speedup 1.0000x reference)
#include <cuda_runtime.h>

#define HH 200
#define WW 304
#define CC 256
#define NOUT 7
#define NSAMP 14          // NOUT * RATIO
#define NCORN 28          // 2 * NSAMP
#define TPITCH 36         // padded tile pitch (floats)
#define WARPS 8
#define CH_PER_BLOCK 64   // CC / CSPLIT
#define CSPLIT 4

__global__ __launch_bounds__(256, 5)
void roi_align_kernel(const float* __restrict__ feat,
                      const float* __restrict__ boxes,
                      float* __restrict__ out)
{
    __shared__ int   s_cx[NCORN];
    __shared__ float s_fx[NSAMP];
    __shared__ int   s_vx[NSAMP];
    __shared__ int   s_cy[NCORN];
    __shared__ __align__(16) float s_wy[NCORN];   // separable y weight * validity
    __shared__ __align__(16) float tile[WARPS][NOUT * TPITCH];

    const int r   = blockIdx.x;
    const int tid = threadIdx.x;

    // ---- per-ROI bilinear metadata (threads 0..27) ----
    if (tid < 2 * NSAMP) {
        const int axis = tid / NSAMP;     // 0 = y, 1 = x
        const int i    = tid % NSAMP;
        const float b0 = boxes[r * 4 + (axis ? 0 : 1)] * 0.25f;  // x1 / y1
        const float b1 = boxes[r * 4 + (axis ? 2 : 3)] * 0.25f;  // x2 / y2
        const float len = fmaxf(b1 - b0, 1.0f);
        const float t   = b0 + (i + 0.5f) * 0.5f * (len / 7.0f);
        const int size  = axis ? WW : HH;
        const int valid = (t > -1.0f) && (t < (float)size);
        const float tc  = t < 0.0f ? 0.0f : t;
        const float low = floorf(tc);
        int lo, hi; float frac;
        if (low >= (float)(size - 1)) {
            lo = size - 1; hi = size - 1; frac = 0.0f;
        } else {
            lo = (int)low; hi = lo + 1; frac = tc - low;
        }
        if (axis) {
            s_cx[2 * i] = lo; s_cx[2 * i + 1] = hi; s_fx[i] = frac; s_vx[i] = valid;
        } else {
            const float vm = valid ? 1.0f : 0.0f;
            s_cy[2 * i]     = lo;
            s_cy[2 * i + 1] = hi;
            s_wy[2 * i]     = (1.0f - frac) * vm;
            s_wy[2 * i + 1] = frac * vm;
        }
    }
    __syncthreads();

    const int warp = tid >> 5;
    const int lane = tid & 31;
    const int img  = r >> 9;                       // r / 512
    const float* fb = feat + (size_t)img * CC * HH * WW;
    float* tw = tile[warp];
    const int c0 = blockIdx.y * CH_PER_BLOCK;

    // Per-lane x-corner column + separable x weight (frac * validity).
    // Lanes 28-31 mirror lane 27 (same addresses -> no extra cache lines;
    // their tile writes land in padding cols 28-35, never read).
    const int cidx = lane < NCORN ? lane : NCORN - 1;
    const int mycx = s_cx[cidx];
    float wx;
    {
        const int sx = cidx >> 1;
        const float fx = s_fx[sx];
        wx = ((cidx & 1) ? fx : 1.0f - fx) * (s_vx[sx] ? 1.0f : 0.0f);
    }

    // Row offsets packed as u16 pairs: rowoff = cy*WW + mycx <= 60799 < 2^16.
    // 14 registers instead of 28.
    unsigned int pk[NCORN / 2];
    #pragma unroll
    for (int i = 0; i < NCORN / 2; i++) {
        const unsigned int o0 = (unsigned int)(s_cy[2 * i]     * WW + mycx);
        const unsigned int o1 = (unsigned int)(s_cy[2 * i + 1] * WW + mycx);
        pk[i] = o0 | (o1 << 16);
    }

    for (int c = c0 + warp; c < c0 + CH_PER_BLOCK; c += WARPS) {
        const float* fc = fb + (size_t)c * (HH * WW);

        // gather + y-fold, 4 rows per output row-group; wy read as float4 broadcast
        #pragma unroll
        for (int q = 0; q < NOUT; q++) {
            const float4 w4 = *(const float4*)(s_wy + 4 * q);
            const unsigned int p0 = pk[2 * q];
            const unsigned int p1 = pk[2 * q + 1];
            float acc;
            acc =      w4.x * __ldg(fc + (p0 & 0xFFFFu));
            acc = fmaf(w4.y,  __ldg(fc + (p0 >> 16)),    acc);
            acc = fmaf(w4.z,  __ldg(fc + (p1 & 0xFFFFu)), acc);
            acc = fmaf(w4.w,  __ldg(fc + (p1 >> 16)),    acc);
            tw[q * TPITCH + lane] = acc * wx;
        }
        __syncwarp();

        // bins: 1 LDS.128 + horizontal add each
        float* ob = out + ((size_t)r * CC + c) * (NOUT * NOUT);
        #pragma unroll
        for (int bb = 0; bb < 2; bb++) {
            const int bin = lane + bb * 32;
            if (bin < NOUT * NOUT) {
                const int py = bin / NOUT;
                const int px = bin - py * NOUT;
                const float4 v = *(const float4*)(tw + py * TPITCH + 4 * px);
                ob[bin] = (v.x + v.y + v.z + v.w) * 0.25f;
            }
        }
        __syncwarp();
    }
}

extern "C" void kernel_launch(void* const* d_in, const int* in_sizes, int n_in,
                              void* d_out, int out_size)
{
    const float* feat  = (const float*)d_in[0];   // (2,256,200,304) f32
    const float* boxes = (const float*)d_in[1];   // (2,512,4) f32
    float* out = (float*)d_out;                   // (1024,256,7,7) f32

    dim3 grid(1024, CSPLIT);
    dim3 block(256);
    roi_align_kernel<<<grid, block>>>(feat, boxes, out);
}

// round 9
// speedup vs baseline: 1.1688x; 1.1688x over previous
#include <cuda_runtime.h>

#define HH 200
#define WW 304
#define CC 256
#define NOUT 7
#define NSAMP 14          // NOUT * RATIO
#define NCORN 28          // 2 * NSAMP
#define TPITCH 36         // padded tile pitch (floats)
#define WARPS 8
#define CH_PER_BLOCK 64   // CC / CSPLIT
#define CSPLIT 4

__global__ __launch_bounds__(256, 4)
void roi_align_kernel(const float* __restrict__ feat,
                      const float* __restrict__ boxes,
                      float* __restrict__ out)
{
    __shared__ int   s_cx[NCORN];
    __shared__ float s_fx[NSAMP];
    __shared__ int   s_vx[NSAMP];
    __shared__ int   s_cy[NCORN];
    __shared__ __align__(16) float s_wy[NCORN];   // separable y weight * validity
    __shared__ __align__(16) float tile[WARPS][NOUT * TPITCH];

    const int r   = blockIdx.x;
    const int tid = threadIdx.x;

    // ---- per-ROI bilinear metadata (threads 0..27) ----
    if (tid < 2 * NSAMP) {
        const int axis = tid / NSAMP;     // 0 = y, 1 = x
        const int i    = tid % NSAMP;
        const float b0 = boxes[r * 4 + (axis ? 0 : 1)] * 0.25f;  // x1 / y1
        const float b1 = boxes[r * 4 + (axis ? 2 : 3)] * 0.25f;  // x2 / y2
        const float len = fmaxf(b1 - b0, 1.0f);
        const float t   = b0 + (i + 0.5f) * 0.5f * (len / 7.0f);
        const int size  = axis ? WW : HH;
        const int valid = (t > -1.0f) && (t < (float)size);
        const float tc  = t < 0.0f ? 0.0f : t;
        const float low = floorf(tc);
        int lo, hi; float frac;
        if (low >= (float)(size - 1)) {
            lo = size - 1; hi = size - 1; frac = 0.0f;
        } else {
            lo = (int)low; hi = lo + 1; frac = tc - low;
        }
        if (axis) {
            s_cx[2 * i] = lo; s_cx[2 * i + 1] = hi; s_fx[i] = frac; s_vx[i] = valid;
        } else {
            const float vm = valid ? 1.0f : 0.0f;
            s_cy[2 * i]     = lo;
            s_cy[2 * i + 1] = hi;
            s_wy[2 * i]     = (1.0f - frac) * vm;
            s_wy[2 * i + 1] = frac * vm;
        }
    }
    __syncthreads();

    const int warp = tid >> 5;
    const int lane = tid & 31;
    const int img  = r >> 9;                       // r / 512
    const float* fb = feat + (size_t)img * CC * HH * WW;
    float* tw = tile[warp];
    const int c0 = blockIdx.y * CH_PER_BLOCK;

    // Per-lane x-corner column + separable x weight (frac * validity).
    // Lanes 28-31 mirror lane 27 (same addresses; tile writes land in padding).
    const int cidx = lane < NCORN ? lane : NCORN - 1;
    const int mycx = s_cx[cidx];
    float wx;
    {
        const int sx = cidx >> 1;
        const float fx = s_fx[sx];
        wx = ((cidx & 1) ? fx : 1.0f - fx) * (s_vx[sx] ? 1.0f : 0.0f);
    }

    // Per-lane absolute row offsets (plain int registers — R6 configuration).
    int rowoff[NCORN];
    #pragma unroll
    for (int a = 0; a < NCORN; a++) rowoff[a] = s_cy[a] * WW + mycx;

    for (int c = c0 + warp; c < c0 + CH_PER_BLOCK; c += WARPS) {
        const float* fc = fb + (size_t)c * (HH * WW);

        // gather + y-fold, 4 rows per output row-group; wy via float4 broadcast
        #pragma unroll
        for (int q = 0; q < NOUT; q++) {
            const float4 w4 = *(const float4*)(s_wy + 4 * q);
            float acc;
            acc =      w4.x * __ldg(fc + rowoff[4 * q + 0]);
            acc = fmaf(w4.y,  __ldg(fc + rowoff[4 * q + 1]), acc);
            acc = fmaf(w4.z,  __ldg(fc + rowoff[4 * q + 2]), acc);
            acc = fmaf(w4.w,  __ldg(fc + rowoff[4 * q + 3]), acc);
            tw[q * TPITCH + lane] = acc * wx;
        }
        __syncwarp();

        // bins: 1 LDS.128 + horizontal add each
        float* ob = out + ((size_t)r * CC + c) * (NOUT * NOUT);
        #pragma unroll
        for (int bb = 0; bb < 2; bb++) {
            const int bin = lane + bb * 32;
            if (bin < NOUT * NOUT) {
                const int py = bin / NOUT;
                const int px = bin - py * NOUT;
                const float4 v = *(const float4*)(tw + py * TPITCH + 4 * px);
                ob[bin] = (v.x + v.y + v.z + v.w) * 0.25f;
            }
        }
        __syncwarp();
    }
}

extern "C" void kernel_launch(void* const* d_in, const int* in_sizes, int n_in,
                              void* d_out, int out_size)
{
    const float* feat  = (const float*)d_in[0];   // (2,256,200,304) f32
    const float* boxes = (const float*)d_in[1];   // (2,512,4) f32
    float* out = (float*)d_out;                   // (1024,256,7,7) f32

    dim3 grid(1024, CSPLIT);
    dim3 block(256);
    roi_align_kernel<<<grid, block>>>(feat, boxes, out);
}